// round 5
// baseline (speedup 1.0000x reference)
#include <cuda_runtime.h>
#include <cuda_bf16.h>

// Output: pos[b=32, F=512, h=64, w=64] fp32.
// pos[b][f][i][j] = row_embed[Z(i,j)][f],  Z = max(|32-j| + |32-i| - 1, 0) in [0,63].
// Key fact: the plane is identical for all 32 batches -> compute once into
// registers, replay STG.128 across batches. Steady state = pure stores.

static constexpr int NUM_POS_FEATS = 512;  // F
static constexpr int LEN_EMB       = 64;
static constexpr int PLANE_F4      = 1024;          // 64*64 floats / 4
static constexpr int BATCH_STRIDE_F4 = NUM_POS_FEATS * PLANE_F4;  // float4 per batch
static constexpr int B_PER_CTA     = 8;             // 32 batches / gridDim.y(4)

__global__ __launch_bounds__(256, 8)
void pe_kernel(const float* __restrict__ row_embed, float* __restrict__ out) {
    __shared__ float s[LEN_EMB];

    const int f   = blockIdx.x;            // 0..511
    const int b0  = blockIdx.y * B_PER_CTA; // 0,8,16,24
    const int tid = threadIdx.x;

    if (tid < LEN_EMB) s[tid] = row_embed[tid * NUM_POS_FEATS + f];
    __syncthreads();

    // Compute this thread's 4 float4 values once.
    float4 v[4];
    #pragma unroll
    for (int k = 0; k < 4; k++) {
        const int p  = tid + k * 256;      // float4 index 0..1023 in plane
        const int i  = p >> 4;             // row
        const int j0 = (p & 15) << 2;      // col base
        const int di = abs(32 - i) - 1;
        v[k].x = s[max(di + abs(32 - (j0 + 0)), 0)];
        v[k].y = s[max(di + abs(32 - (j0 + 1)), 0)];
        v[k].z = s[max(di + abs(32 - (j0 + 2)), 0)];
        v[k].w = s[max(di + abs(32 - (j0 + 3)), 0)];
    }

    // Replay stores across this CTA's batches: pure STG.128 stream.
    float4* o = reinterpret_cast<float4*>(out)
              + (size_t)b0 * BATCH_STRIDE_F4
              + (size_t)f  * PLANE_F4 + tid;

    #pragma unroll
    for (int b = 0; b < B_PER_CTA; b++) {
        o[0]   = v[0];
        o[256] = v[1];
        o[512] = v[2];
        o[768] = v[3];
        o += BATCH_STRIDE_F4;
    }
}

extern "C" void kernel_launch(void* const* d_in, const int* in_sizes, int n_in,
                              void* d_out, int out_size) {
    // d_in[0] = x (shape-only, unused), d_in[1] = row_embed [64, 512] fp32
    const float* row_embed = (const float*)d_in[1];
    float* out = (float*)d_out;

    dim3 grid(NUM_POS_FEATS, 4);   // 2048 CTAs, each: 1 plane x 8 batches
    pe_kernel<<<grid, 256>>>(row_embed, out);
}

// round 6
// speedup vs baseline: 1.0711x; 1.0711x over previous
#include <cuda_runtime.h>
#include <cuda_bf16.h>

// Output: pos[b=32, F=512, h=64, w=64] fp32.
// pos[b][f][i][j] = row_embed[Z(i,j)][f],  Z = max(|32-j| + |32-i| - 1, 0) in [0,63].
// Plane identical across batches. Compute once into registers, replay stores
// across a SMALL batch group (2) so the concurrent-wave write footprint stays
// dense (L2/DRAM locality) while halving LDS traffic in the L1tex pipe.

static constexpr int NUM_POS_FEATS   = 512;   // F
static constexpr int LEN_EMB         = 64;
static constexpr int PLANE_F4        = 1024;  // 64*64 floats / 4
static constexpr int BATCH_STRIDE_F4 = NUM_POS_FEATS * PLANE_F4;
static constexpr int B_PER_CTA       = 2;     // 32 batches / gridDim.y(16)

__global__ __launch_bounds__(256, 8)
void pe_kernel(const float* __restrict__ row_embed, float* __restrict__ out) {
    __shared__ float s[LEN_EMB];

    const int f   = blockIdx.x;                 // 0..511
    const int b0  = blockIdx.y * B_PER_CTA;     // 0,2,...,30
    const int tid = threadIdx.x;

    if (tid < LEN_EMB) s[tid] = row_embed[tid * NUM_POS_FEATS + f];
    __syncthreads();

    // Compute this thread's 4 float4 values once.
    float4 v[4];
    #pragma unroll
    for (int k = 0; k < 4; k++) {
        const int p  = tid + k * 256;      // float4 index 0..1023 in plane
        const int i  = p >> 4;             // row
        const int j0 = (p & 15) << 2;      // col base
        const int di = abs(32 - i) - 1;
        v[k].x = s[max(di + abs(32 - (j0 + 0)), 0)];
        v[k].y = s[max(di + abs(32 - (j0 + 1)), 0)];
        v[k].z = s[max(di + abs(32 - (j0 + 2)), 0)];
        v[k].w = s[max(di + abs(32 - (j0 + 3)), 0)];
    }

    // Store to 2 batches: 8 x STG.128 per thread.
    float4* o = reinterpret_cast<float4*>(out)
              + (size_t)b0 * BATCH_STRIDE_F4
              + (size_t)f  * PLANE_F4 + tid;

    #pragma unroll
    for (int b = 0; b < B_PER_CTA; b++) {
        o[0]   = v[0];
        o[256] = v[1];
        o[512] = v[2];
        o[768] = v[3];
        o += BATCH_STRIDE_F4;
    }
}

extern "C" void kernel_launch(void* const* d_in, const int* in_sizes, int n_in,
                              void* d_out, int out_size) {
    // d_in[0] = x (shape-only, unused), d_in[1] = row_embed [64, 512] fp32
    const float* row_embed = (const float*)d_in[1];
    float* out = (float*)d_out;

    dim3 grid(NUM_POS_FEATS, 16);  // 8192 CTAs: 1 plane x 2 batches each
    pe_kernel<<<grid, 256>>>(row_embed, out);
}